// round 5
// baseline (speedup 1.0000x reference)
#include <cuda_runtime.h>

#define NHEADS 4

// Scratch (allocation-free: __device__ globals)
__device__ float g_atil[NHEADS][64];   // (scale*log2e) * W2^T Wk_h^T q_h
__device__ float g_S[NHEADS][64];      // sum_n w[h,n] * u_n
__device__ float g_z[NHEADS];          // sum_n w[h,n]

__device__ __forceinline__ float tanh_fast(float x) {
    float y; asm("tanh.approx.f32 %0, %1;" : "=f"(y) : "f"(x)); return y;
}
__device__ __forceinline__ float exp2_fast(float x) {
    float y; asm("ex2.approx.f32 %0, %1;" : "=f"(y) : "f"(x)); return y;
}

// ---------------------------------------------------------------------------
// Kernel 0: precompute score vectors, zero accumulators. 1 block, 64 threads.
// ---------------------------------------------------------------------------
__global__ void setup_kernel(const float* __restrict__ W2,
                             const float* __restrict__ query,
                             const float* __restrict__ ipw,
                             const float* __restrict__ ipb) {
    __shared__ float qv[64];
    __shared__ float a[NHEADS][64];
    int t = threadIdx.x;  // 0..63
    // q = query @ Wq^T + bq   (Wq = in_proj_w rows [0,64))
    float s = ipb[t];
    #pragma unroll 8
    for (int l = 0; l < 64; ++l) s = fmaf(query[l], ipw[t * 64 + l], s);
    qv[t] = s;
    __syncthreads();
    // a_h[m] = sum_{d<16} q[16h+d] * Wk[16h+d, m]   (Wk = rows [64,128))
    #pragma unroll
    for (int h = 0; h < NHEADS; ++h) {
        float ah = 0.f;
        #pragma unroll 4
        for (int d = 0; d < 16; ++d)
            ah = fmaf(qv[16 * h + d], ipw[(64 + 16 * h + d) * 64 + t], ah);
        a[h][t] = ah;
    }
    __syncthreads();
    // atil_h[j] = scale*log2(e) * sum_m a_h[m] * W2[m, j];  scale = 1/sqrt(16)
    const float scale = 0.25f * 1.4426950408889634f;  // fold log2(e): exp2(p)=exp(score)
    #pragma unroll
    for (int h = 0; h < NHEADS; ++h) {
        float s2 = 0.f;
        #pragma unroll 8
        for (int m = 0; m < 64; ++m)
            s2 = fmaf(a[h][m], W2[m * 64 + t], s2);
        g_atil[h][t] = s2 * scale;
        g_S[h][t] = 0.f;
    }
    if (t < NHEADS) g_z[t] = 0.f;
}

// ---------------------------------------------------------------------------
// Main kernel: warp cooperates; lane l owns hidden dims l, l+32.
// 8 points per round: 8pt x 4heads = 32 partial scores -> one halving
// butterfly reduces all of them; score(pt,h) lands at lane 4*pt+h.
// ---------------------------------------------------------------------------
__global__ void __launch_bounds__(256)
main_kernel(const float* __restrict__ rr,
            const float* __restrict__ ri,
            const float* __restrict__ W1,
            const float* __restrict__ b1,
            int N) {
    const int lane   = threadIdx.x & 31;
    const int gwarp  = (blockIdx.x * blockDim.x + threadIdx.x) >> 5;
    const int nwarps = (gridDim.x * blockDim.x) >> 5;
    const int j0 = lane, j1 = lane + 32;

    const float w1a0 = W1[2 * j0], w1b0 = W1[2 * j0 + 1], c0 = b1[j0];
    const float w1a1 = W1[2 * j1], w1b1 = W1[2 * j1 + 1], c1 = b1[j1];
    float A0[NHEADS], A1[NHEADS];
    #pragma unroll
    for (int h = 0; h < NHEADS; ++h) { A0[h] = g_atil[h][j0]; A1[h] = g_atil[h][j1]; }

    float acc0[NHEADS] = {0.f, 0.f, 0.f, 0.f};
    float acc1[NHEADS] = {0.f, 0.f, 0.f, 0.f};
    float zz[NHEADS]   = {0.f, 0.f, 0.f, 0.f};

    const int G = N >> 3;                      // groups of 8 points
    const int chunk = (G + nwarps - 1) / nwarps;
    const int gs = gwarp * chunk;
    const int ge = min(G, gs + chunk);

    const float4* rr4 = (const float4*)rr;
    const float4* ri4 = (const float4*)ri;

    for (int g = gs; g < ge; ++g) {
        float4 ra = __ldg(rr4 + 2 * g), rb = __ldg(rr4 + 2 * g + 1);
        float4 ia = __ldg(ri4 + 2 * g), ib = __ldg(ri4 + 2 * g + 1);
        float re[8] = {ra.x, ra.y, ra.z, ra.w, rb.x, rb.y, rb.z, rb.w};
        float im[8] = {ia.x, ia.y, ia.z, ia.w, ib.x, ib.y, ib.z, ib.w};
        float u0[8], u1[8], p[32];
        #pragma unroll
        for (int pt = 0; pt < 8; ++pt) {
            float t0 = fmaf(w1a0, re[pt], fmaf(w1b0, im[pt], c0));
            float t1 = fmaf(w1a1, re[pt], fmaf(w1b1, im[pt], c1));
            // silu(t) = t/2 + (t/2)*tanh(t/2)
            float h0 = 0.5f * t0, h1 = 0.5f * t1;
            float v0 = fmaf(h0, tanh_fast(h0), h0);
            float v1 = fmaf(h1, tanh_fast(h1), h1);
            u0[pt] = v0; u1[pt] = v1;
            #pragma unroll
            for (int h = 0; h < NHEADS; ++h)
                p[pt * 4 + h] = fmaf(A0[h], v0, A1[h] * v1);
        }
        // Halving butterfly: 32 independent warp-sums in 31 shfls.
        // After stage m, active values are [0, m); lane l ends holding the
        // full warp-sum of value index l in p[0].
        #pragma unroll
        for (int m = 16; m >= 1; m >>= 1) {
            const bool hi = (lane & m) != 0;
            #pragma unroll
            for (int i = 0; i < m; ++i) {
                float keep = hi ? p[i + m] : p[i];
                float send = hi ? p[i] : p[i + m];
                p[i] = keep + __shfl_xor_sync(0xffffffffu, send, m);
            }
        }
        float em = exp2_fast(p[0]);   // = exp(score(pt=lane>>2, h=lane&3))
        #pragma unroll
        for (int pt = 0; pt < 8; ++pt) {
            #pragma unroll
            for (int h = 0; h < NHEADS; ++h) {
                float w = __shfl_sync(0xffffffffu, em, pt * 4 + h);
                zz[h] += w;
                acc0[h] = fmaf(w, u0[pt], acc0[h]);
                acc1[h] = fmaf(w, u1[pt], acc1[h]);
            }
        }
    }

    // Tail points (N % 8), handled by warp 0 with per-point butterfly.
    if (gwarp == 0) {
        for (int n = (G << 3); n < N; ++n) {
            float re = rr[n], im = ri[n];
            float t0 = fmaf(w1a0, re, fmaf(w1b0, im, c0));
            float t1 = fmaf(w1a1, re, fmaf(w1b1, im, c1));
            float h0 = 0.5f * t0, h1 = 0.5f * t1;
            float v0 = fmaf(h0, tanh_fast(h0), h0);
            float v1 = fmaf(h1, tanh_fast(h1), h1);
            #pragma unroll
            for (int h = 0; h < NHEADS; ++h) {
                float s = fmaf(A0[h], v0, A1[h] * v1);
                #pragma unroll
                for (int m = 16; m >= 1; m >>= 1)
                    s += __shfl_xor_sync(0xffffffffu, s, m);
                float w = exp2_fast(s);
                zz[h] += w;
                acc0[h] = fmaf(w, v0, acc0[h]);
                acc1[h] = fmaf(w, v1, acc1[h]);
            }
        }
    }

    // Commit warp partials (lane-distinct addresses -> no intra-warp contention)
    #pragma unroll
    for (int h = 0; h < NHEADS; ++h) {
        atomicAdd(&g_S[h][j0], acc0[h]);
        atomicAdd(&g_S[h][j1], acc1[h]);
    }
    if (lane == 0) {
        #pragma unroll
        for (int h = 0; h < NHEADS; ++h) atomicAdd(&g_z[h], zz[h]);
    }
}

// ---------------------------------------------------------------------------
// Finalize: hbar_h = W2 (S_h/z_h) + b2; pooled; out-proj. 1 block, 64 threads.
// ---------------------------------------------------------------------------
__global__ void fin_kernel(const float* __restrict__ W2, const float* __restrict__ b2,
                           const float* __restrict__ ipw, const float* __restrict__ ipb,
                           const float* __restrict__ opw, const float* __restrict__ opb,
                           float* __restrict__ out) {
    __shared__ float hbar[NHEADS][64];
    __shared__ float pooled[64];
    int t = threadIdx.x;  // 0..63
    float invz[NHEADS];
    #pragma unroll
    for (int h = 0; h < NHEADS; ++h) invz[h] = __frcp_rn(g_z[h]);
    #pragma unroll
    for (int h = 0; h < NHEADS; ++h) {
        float s = 0.f;
        #pragma unroll 8
        for (int j = 0; j < 64; ++j) s = fmaf(W2[t * 64 + j], g_S[h][j], s);
        hbar[h][t] = fmaf(s, invz[h], b2[t]);
    }
    __syncthreads();
    {
        // pooled[16h+d] = Wv row (128+16h+d) dot hbar_h + bv
        int h = t >> 4;
        float s = ipb[128 + t];
        #pragma unroll 8
        for (int m = 0; m < 64; ++m) s = fmaf(ipw[(128 + t) * 64 + m], hbar[h][m], s);
        pooled[t] = s;
    }
    __syncthreads();
    float s = opb[t];
    #pragma unroll 8
    for (int k = 0; k < 64; ++k) s = fmaf(opw[t * 64 + k], pooled[k], s);
    out[t] = s;
}

// ---------------------------------------------------------------------------
extern "C" void kernel_launch(void* const* d_in, const int* in_sizes, int n_in,
                              void* d_out, int out_size) {
    // Inputs (metadata order): rho_real, rho_imag, l_A, l_B, [Z_A, Z_B,]
    // W1, b1, W2, b2, query, in_proj_w, in_proj_b, out_proj_w, out_proj_b.
    // Index the trailing 9 from the end to be robust to scalar handling.
    const float* rr    = (const float*)d_in[0];
    const float* ri    = (const float*)d_in[1];
    const float* W1    = (const float*)d_in[n_in - 9];
    const float* b1    = (const float*)d_in[n_in - 8];
    const float* W2    = (const float*)d_in[n_in - 7];
    const float* b2    = (const float*)d_in[n_in - 6];
    const float* query = (const float*)d_in[n_in - 5];
    const float* ipw   = (const float*)d_in[n_in - 4];
    const float* ipb   = (const float*)d_in[n_in - 3];
    const float* opw   = (const float*)d_in[n_in - 2];
    const float* opb   = (const float*)d_in[n_in - 1];
    int N = in_sizes[0];

    setup_kernel<<<1, 64>>>(W2, query, ipw, ipb);
    main_kernel<<<296, 256>>>(rr, ri, W1, b1, N);
    fin_kernel<<<1, 64>>>(W2, b2, ipw, ipb, opw, opb, (float*)d_out);
}

// round 6
// speedup vs baseline: 1.1387x; 1.1387x over previous
#include <cuda_runtime.h>

#define NHEADS 4
typedef unsigned long long u64;

// Scratch (allocation-free). Zero at module load; fin_kernel re-zeroes after
// reading so every graph replay observes zeros (deterministic).
__device__ float g_S[NHEADS][64];      // sum_n w[h,n] * u_n
__device__ float g_z[NHEADS];          // sum_n w[h,n]

__device__ __forceinline__ float tanh_fast(float x) {
    float y; asm("tanh.approx.f32 %0, %1;" : "=f"(y) : "f"(x)); return y;
}
__device__ __forceinline__ float exp2_fast(float x) {
    float y; asm("ex2.approx.f32 %0, %1;" : "=f"(y) : "f"(x)); return y;
}
// ---- packed f32x2 helpers (ptxas never auto-fuses these from C++) ----
__device__ __forceinline__ u64 pack2(float lo, float hi) {
    u64 r; asm("mov.b64 %0, {%1, %2};" : "=l"(r) : "f"(lo), "f"(hi)); return r;
}
__device__ __forceinline__ void unpack2(u64 v, float& lo, float& hi) {
    asm("mov.b64 {%0, %1}, %2;" : "=f"(lo), "=f"(hi) : "l"(v));
}
__device__ __forceinline__ u64 fma2(u64 a, u64 b, u64 c) {
    u64 d; asm("fma.rn.f32x2 %0, %1, %2, %3;" : "=l"(d) : "l"(a), "l"(b), "l"(c)); return d;
}
__device__ __forceinline__ u64 mul2(u64 a, u64 b) {
    u64 d; asm("mul.rn.f32x2 %0, %1, %2;" : "=l"(d) : "l"(a), "l"(b)); return d;
}

// ---------------------------------------------------------------------------
// Main kernel. Prologue: every block computes atil[h][j] =
// (scale*log2e) * (W2^T Wk_h^T q_h)[j] into shared memory (L2-hot, ~cheap,
// replaces the 19us serial setup kernel).
// Main loop: warp cooperates; lane l owns hidden dims j0=l, j1=l+32.
// 8 points / round; MLP+scores packed f32x2; 32 scores reduced by one
// 31-shfl halving butterfly; score(pt,h) lands at lane 4*pt+h.
// ---------------------------------------------------------------------------
__global__ void __launch_bounds__(256, 2)
main_kernel(const float* __restrict__ rr,
            const float* __restrict__ ri,
            const float* __restrict__ W1,
            const float* __restrict__ b1,
            const float* __restrict__ W2,
            const float* __restrict__ query,
            const float* __restrict__ ipw,
            const float* __restrict__ ipb,
            int N) {
    __shared__ float qsh[64];
    __shared__ float ash[NHEADS][64];
    __shared__ float atil[NHEADS][64];

    const int t    = threadIdx.x;
    const int lane = t & 31;

    // ---- prologue: q = query @ Wq^T + bq (4 threads per output) ----
    {
        int o = t >> 2, part = t & 3;
        float s = 0.f;
        const float* row = ipw + o * 64 + part * 16;
        const float* qp  = query + part * 16;
        #pragma unroll
        for (int i = 0; i < 16; ++i) s = fmaf(qp[i], row[i], s);
        s += __shfl_xor_sync(0xffffffffu, s, 1);
        s += __shfl_xor_sync(0xffffffffu, s, 2);
        if (part == 0) qsh[o] = s + ipb[o];
    }
    __syncthreads();
    // ---- a_h[c] = sum_d q[16h+d] * Wk[16h+d, c]  (Wk = ipw rows [64,128)) ----
    {
        int h = t >> 6, c = t & 63;
        float a = 0.f;
        #pragma unroll 4
        for (int d = 0; d < 16; ++d)
            a = fmaf(qsh[16 * h + d], ipw[(64 + 16 * h + d) * 64 + c], a);
        ash[h][c] = a;
    }
    __syncthreads();
    // ---- atil_h[c] = (0.25*log2e) * sum_m a_h[m] * W2[m,c] ----
    {
        const float SC = 0.25f * 1.4426950408889634f;  // scale * log2(e)
        int h = t >> 6, c = t & 63;
        float s = 0.f;
        #pragma unroll 8
        for (int m = 0; m < 64; ++m) s = fmaf(ash[h][m], W2[m * 64 + c], s);
        atil[h][c] = s * SC;
    }
    __syncthreads();

    // ---- per-lane constants (SiLU's 0.5 folded into W1/b1) ----
    const int j0 = lane, j1 = lane + 32;
    const u64 KA0 = pack2(0.5f * W1[2 * j0], 0.5f * W1[2 * j0]);
    const u64 KB0 = pack2(0.5f * W1[2 * j0 + 1], 0.5f * W1[2 * j0 + 1]);
    const u64 KC0 = pack2(0.5f * b1[j0], 0.5f * b1[j0]);
    const u64 KA1 = pack2(0.5f * W1[2 * j1], 0.5f * W1[2 * j1]);
    const u64 KB1 = pack2(0.5f * W1[2 * j1 + 1], 0.5f * W1[2 * j1 + 1]);
    const u64 KC1 = pack2(0.5f * b1[j1], 0.5f * b1[j1]);
    u64 AH0[NHEADS], AH1[NHEADS];
    #pragma unroll
    for (int h = 0; h < NHEADS; ++h) {
        AH0[h] = pack2(atil[h][j0], atil[h][j0]);
        AH1[h] = pack2(atil[h][j1], atil[h][j1]);
    }

    float acc0[NHEADS] = {0.f, 0.f, 0.f, 0.f};
    float acc1[NHEADS] = {0.f, 0.f, 0.f, 0.f};
    float zloc = 0.f;          // lane-local: sum of this lane's own em values

    const int gwarp  = (blockIdx.x * blockDim.x + t) >> 5;
    const int nwarps = (gridDim.x * blockDim.x) >> 5;
    const int G = N >> 3;
    const int chunk = (G + nwarps - 1) / nwarps;
    const int gs = gwarp * chunk;
    const int ge = min(G, gs + chunk);

    const float4* rr4 = (const float4*)rr;
    const float4* ri4 = (const float4*)ri;

    for (int g = gs; g < ge; ++g) {
        float4 ra = __ldg(rr4 + 2 * g), rb = __ldg(rr4 + 2 * g + 1);
        float4 ia = __ldg(ri4 + 2 * g), ib = __ldg(ri4 + 2 * g + 1);
        u64 re2[4] = {pack2(ra.x, ra.y), pack2(ra.z, ra.w),
                      pack2(rb.x, rb.y), pack2(rb.z, rb.w)};
        u64 im2[4] = {pack2(ia.x, ia.y), pack2(ia.z, ia.w),
                      pack2(ib.x, ib.y), pack2(ib.z, ib.w)};
        float u0s[8], u1s[8], p[32];
        #pragma unroll
        for (int q = 0; q < 4; ++q) {
            u64 h0 = fma2(KA0, re2[q], fma2(KB0, im2[q], KC0));   // t/2 pair
            u64 h1 = fma2(KA1, re2[q], fma2(KB1, im2[q], KC1));
            float h0l, h0h, h1l, h1h;
            unpack2(h0, h0l, h0h); unpack2(h1, h1l, h1h);
            u64 th0 = pack2(tanh_fast(h0l), tanh_fast(h0h));
            u64 th1 = pack2(tanh_fast(h1l), tanh_fast(h1h));
            u64 v0 = fma2(h0, th0, h0);    // silu = h + h*tanh(h), h = t/2
            u64 v1 = fma2(h1, th1, h1);
            unpack2(v0, u0s[2 * q], u0s[2 * q + 1]);
            unpack2(v1, u1s[2 * q], u1s[2 * q + 1]);
            #pragma unroll
            for (int h = 0; h < NHEADS; ++h) {
                u64 sc = fma2(AH0[h], v0, mul2(AH1[h], v1));
                unpack2(sc, p[(2 * q) * 4 + h], p[(2 * q + 1) * 4 + h]);
            }
        }
        // Halving butterfly: 32 warp-sums in 31 shfls; lane l ends with the
        // warp-sum of p[l] in p[0]  (score for pt=l>>2, h=l&3).
        #pragma unroll
        for (int m = 16; m >= 1; m >>= 1) {
            const bool hi = (lane & m) != 0;
            #pragma unroll
            for (int i = 0; i < m; ++i) {
                float keep = hi ? p[i + m] : p[i];
                float send = hi ? p[i] : p[i + m];
                p[i] = keep + __shfl_xor_sync(0xffffffffu, send, m);
            }
        }
        float em = exp2_fast(p[0]);   // exp(score(pt=lane>>2, h=lane&3))
        zloc += em;
        #pragma unroll
        for (int pt = 0; pt < 8; ++pt) {
            float v0 = u0s[pt], v1 = u1s[pt];
            #pragma unroll
            for (int h = 0; h < NHEADS; ++h) {
                float w = __shfl_sync(0xffffffffu, em, pt * 4 + h);
                acc0[h] = fmaf(w, v0, acc0[h]);
                acc1[h] = fmaf(w, v1, acc1[h]);
            }
        }
    }

    // Tail points (N % 8): warp 0 only, scalar path.
    float ztl[NHEADS] = {0.f, 0.f, 0.f, 0.f};
    if (gwarp == 0) {
        float A0[NHEADS], A1[NHEADS];
        #pragma unroll
        for (int h = 0; h < NHEADS; ++h) { A0[h] = atil[h][j0]; A1[h] = atil[h][j1]; }
        float ka0, kb0, kc0, ka1, kb1, kc1, dum;
        unpack2(KA0, ka0, dum); unpack2(KB0, kb0, dum); unpack2(KC0, kc0, dum);
        unpack2(KA1, ka1, dum); unpack2(KB1, kb1, dum); unpack2(KC1, kc1, dum);
        for (int n = (G << 3); n < N; ++n) {
            float re = rr[n], im = ri[n];
            float h0 = fmaf(ka0, re, fmaf(kb0, im, kc0));
            float h1 = fmaf(ka1, re, fmaf(kb1, im, kc1));
            float v0 = fmaf(h0, tanh_fast(h0), h0);
            float v1 = fmaf(h1, tanh_fast(h1), h1);
            #pragma unroll
            for (int h = 0; h < NHEADS; ++h) {
                float s = fmaf(A0[h], v0, A1[h] * v1);
                #pragma unroll
                for (int m = 16; m >= 1; m >>= 1)
                    s += __shfl_xor_sync(0xffffffffu, s, m);
                float w = exp2_fast(s);
                ztl[h] += w;
                acc0[h] = fmaf(w, v0, acc0[h]);
                acc1[h] = fmaf(w, v1, acc1[h]);
            }
        }
    }

    // Commit warp partials (lane-distinct addresses; no intra-warp contention)
    #pragma unroll
    for (int h = 0; h < NHEADS; ++h) {
        atomicAdd(&g_S[h][j0], acc0[h]);
        atomicAdd(&g_S[h][j1], acc1[h]);
    }
    // zloc at lane l belongs to head h=l&3; same-h lanes differ in bits {2,3,4}
    float zs = zloc + __shfl_xor_sync(0xffffffffu, zloc, 16);
    zs += __shfl_xor_sync(0xffffffffu, zs, 8);
    zs += __shfl_xor_sync(0xffffffffu, zs, 4);
    if (lane < NHEADS) atomicAdd(&g_z[lane], zs);
    if (gwarp == 0 && lane == 0) {
        #pragma unroll
        for (int h = 0; h < NHEADS; ++h) atomicAdd(&g_z[h], ztl[h]);
    }
}

// ---------------------------------------------------------------------------
// Finalize: hbar_h = W2 (S_h/z_h) + b2; pooled; out-proj. 1 block, 256 thr.
// Also re-zeroes g_S/g_z AFTER reading them so graph replays stay correct.
// ---------------------------------------------------------------------------
__global__ void fin_kernel(const float* __restrict__ W2, const float* __restrict__ b2,
                           const float* __restrict__ ipw, const float* __restrict__ ipb,
                           const float* __restrict__ opw, const float* __restrict__ opb,
                           float* __restrict__ out) {
    __shared__ float hbar[NHEADS][64];
    __shared__ float pooled[64];
    __shared__ float invz[NHEADS];
    int t = threadIdx.x;  // 0..255
    if (t < NHEADS) invz[t] = __frcp_rn(g_z[t]);
    __syncthreads();
    {
        int h = t >> 6, j = t & 63;
        float s = 0.f;
        #pragma unroll 8
        for (int m = 0; m < 64; ++m) s = fmaf(W2[j * 64 + m], g_S[h][m], s);
        hbar[h][j] = fmaf(s, invz[h], b2[j]);
    }
    __syncthreads();
    // scratch reset for next graph replay (all reads of g_S/g_z are done)
    ((float*)g_S)[t] = 0.f;
    if (t < NHEADS) g_z[t] = 0.f;
    if (t < 64) {
        int h = t >> 4;
        float s = ipb[128 + t];   // Wv row (128+t) dot hbar_h + bv
        #pragma unroll 8
        for (int m = 0; m < 64; ++m) s = fmaf(ipw[(128 + t) * 64 + m], hbar[h][m], s);
        pooled[t] = s;
    }
    __syncthreads();
    if (t < 64) {
        float s = opb[t];
        #pragma unroll 8
        for (int k = 0; k < 64; ++k) s = fmaf(opw[t * 64 + k], pooled[k], s);
        out[t] = s;
    }
}

// ---------------------------------------------------------------------------
extern "C" void kernel_launch(void* const* d_in, const int* in_sizes, int n_in,
                              void* d_out, int out_size) {
    // Inputs (metadata order): rho_real, rho_imag, l_A, l_B, [Z_A, Z_B,]
    // W1, b1, W2, b2, query, in_proj_w, in_proj_b, out_proj_w, out_proj_b.
    const float* rr    = (const float*)d_in[0];
    const float* ri    = (const float*)d_in[1];
    const float* W1    = (const float*)d_in[n_in - 9];
    const float* b1    = (const float*)d_in[n_in - 8];
    const float* W2    = (const float*)d_in[n_in - 7];
    const float* b2    = (const float*)d_in[n_in - 6];
    const float* query = (const float*)d_in[n_in - 5];
    const float* ipw   = (const float*)d_in[n_in - 4];
    const float* ipb   = (const float*)d_in[n_in - 3];
    const float* opw   = (const float*)d_in[n_in - 2];
    const float* opb   = (const float*)d_in[n_in - 1];
    int N = in_sizes[0];

    main_kernel<<<296, 256>>>(rr, ri, W1, b1, W2, query, ipw, ipb, N);
    fin_kernel<<<1, 256>>>(W2, b2, ipw, ipb, opw, opb, (float*)d_out);
}

// round 7
// speedup vs baseline: 1.1944x; 1.0489x over previous
#include <cuda_runtime.h>

#define NHEADS 4
typedef unsigned long long u64;

// Scratch (allocation-free). Zero at module load; epilogue re-zeroes after
// reading so every graph replay observes zeros (deterministic).
__device__ float g_S[NHEADS][64];          // sum_n w[h,n] * u_n
__device__ float g_z[NHEADS];              // sum_n w[h,n]
__device__ unsigned int g_ctr;             // last-block-done counter

__device__ __forceinline__ float tanh_fast(float x) {
    float y; asm("tanh.approx.f32 %0, %1;" : "=f"(y) : "f"(x)); return y;
}
__device__ __forceinline__ float exp2_fast(float x) {
    float y; asm("ex2.approx.f32 %0, %1;" : "=f"(y) : "f"(x)); return y;
}
// ---- packed f32x2 helpers (ptxas never auto-fuses these from C++) ----
__device__ __forceinline__ u64 pack2(float lo, float hi) {
    u64 r; asm("mov.b64 %0, {%1, %2};" : "=l"(r) : "f"(lo), "f"(hi)); return r;
}
__device__ __forceinline__ void unpack2(u64 v, float& lo, float& hi) {
    asm("mov.b64 {%0, %1}, %2;" : "=f"(lo), "=f"(hi) : "l"(v));
}
__device__ __forceinline__ u64 fma2(u64 a, u64 b, u64 c) {
    u64 d; asm("fma.rn.f32x2 %0, %1, %2, %3;" : "=l"(d) : "l"(a), "l"(b), "l"(c)); return d;
}
__device__ __forceinline__ u64 mul2(u64 a, u64 b) {
    u64 d; asm("mul.rn.f32x2 %0, %1, %2;" : "=l"(d) : "l"(a), "l"(b)); return d;
}

// ---------------------------------------------------------------------------
// Single fused kernel.
// Prologue (per block): atil[h][j] = (scale*log2e) * (W2^T Wk_h^T q_h)[j].
// Main loop: warp cooperates; lane l owns hidden dims j0=l, j1=l+32.
//   8 points/round; MLP+scores in packed f32x2; 32 scores reduced by one
//   31-shfl halving butterfly; exp2 weights broadcast via smem LDS.128;
//   accumulation in packed f32x2.
// Epilogue: last finished block (atomic counter) computes hbar/pooled/out
//   and re-zeroes scratch for the next graph replay.
// ---------------------------------------------------------------------------
__global__ void __launch_bounds__(256, 2)
main_kernel(const float* __restrict__ rr,
            const float* __restrict__ ri,
            const float* __restrict__ W1,
            const float* __restrict__ b1,
            const float* __restrict__ W2,
            const float* __restrict__ query,
            const float* __restrict__ ipw,
            const float* __restrict__ ipb,
            const float* __restrict__ b2,
            const float* __restrict__ opw,
            const float* __restrict__ opb,
            float* __restrict__ out,
            int N) {
    __shared__ float qsh[64];
    __shared__ float ash[NHEADS][64];     // reused as hbar in epilogue
    __shared__ float atil[NHEADS][64];
    __shared__ float wb[8][2][32];        // per-warp double-buffered weights
    __shared__ float invz[NHEADS];
    __shared__ bool  isLast;

    const int t    = threadIdx.x;
    const int lane = t & 31;
    const int wid  = t >> 5;

    // ---- prologue: q = query @ Wq^T + bq (4 threads per output) ----
    {
        int o = t >> 2, part = t & 3;
        float s = 0.f;
        const float* row = ipw + o * 64 + part * 16;
        const float* qp  = query + part * 16;
        #pragma unroll
        for (int i = 0; i < 16; ++i) s = fmaf(qp[i], row[i], s);
        s += __shfl_xor_sync(0xffffffffu, s, 1);
        s += __shfl_xor_sync(0xffffffffu, s, 2);
        if (part == 0) qsh[o] = s + ipb[o];
    }
    __syncthreads();
    // ---- a_h[c] = sum_d q[16h+d] * Wk[16h+d, c]  (Wk = ipw rows [64,128)) ----
    {
        int h = t >> 6, c = t & 63;
        float a = 0.f;
        #pragma unroll 4
        for (int d = 0; d < 16; ++d)
            a = fmaf(qsh[16 * h + d], ipw[(64 + 16 * h + d) * 64 + c], a);
        ash[h][c] = a;
    }
    __syncthreads();
    // ---- atil_h[c] = (0.25*log2e) * sum_m a_h[m] * W2[m,c] ----
    {
        const float SC = 0.25f * 1.4426950408889634f;  // scale * log2(e)
        int h = t >> 6, c = t & 63;
        float s = 0.f;
        #pragma unroll 8
        for (int m = 0; m < 64; ++m) s = fmaf(ash[h][m], W2[m * 64 + c], s);
        atil[h][c] = s * SC;
    }
    __syncthreads();

    // ---- per-lane constants (SiLU's 0.5 folded into W1/b1) ----
    const int j0 = lane, j1 = lane + 32;
    const u64 KA0 = pack2(0.5f * W1[2 * j0], 0.5f * W1[2 * j0]);
    const u64 KB0 = pack2(0.5f * W1[2 * j0 + 1], 0.5f * W1[2 * j0 + 1]);
    const u64 KC0 = pack2(0.5f * b1[j0], 0.5f * b1[j0]);
    const u64 KA1 = pack2(0.5f * W1[2 * j1], 0.5f * W1[2 * j1]);
    const u64 KB1 = pack2(0.5f * W1[2 * j1 + 1], 0.5f * W1[2 * j1 + 1]);
    const u64 KC1 = pack2(0.5f * b1[j1], 0.5f * b1[j1]);
    u64 AH0[NHEADS], AH1[NHEADS];
    #pragma unroll
    for (int h = 0; h < NHEADS; ++h) {
        AH0[h] = pack2(atil[h][j0], atil[h][j0]);
        AH1[h] = pack2(atil[h][j1], atil[h][j1]);
    }

    // Packed accumulators: (head pair) x (dim j0/j1)
    u64 acc0_01 = 0, acc0_23 = 0, acc1_01 = 0, acc1_23 = 0;
    float zloc = 0.f;   // lane-local sum of this lane's own em values

    const int gwarp  = (blockIdx.x * blockDim.x + t) >> 5;
    const int nwarps = (gridDim.x * blockDim.x) >> 5;
    const int G = N >> 3;
    const int chunk = (G + nwarps - 1) / nwarps;
    const int gs = gwarp * chunk;
    const int ge = min(G, gs + chunk);

    const float4* rr4 = (const float4*)rr;
    const float4* ri4 = (const float4*)ri;

    for (int g = gs; g < ge; ++g) {
        float4 ra = __ldg(rr4 + 2 * g), rb = __ldg(rr4 + 2 * g + 1);
        float4 ia = __ldg(ri4 + 2 * g), ib = __ldg(ri4 + 2 * g + 1);
        u64 re2[4] = {pack2(ra.x, ra.y), pack2(ra.z, ra.w),
                      pack2(rb.x, rb.y), pack2(rb.z, rb.w)};
        u64 im2[4] = {pack2(ia.x, ia.y), pack2(ia.z, ia.w),
                      pack2(ib.x, ib.y), pack2(ib.z, ib.w)};
        u64 U0[4], U1[4];                 // silu pairs per point-pair
        float p[32];
        #pragma unroll
        for (int q = 0; q < 4; ++q) {
            u64 h0 = fma2(KA0, re2[q], fma2(KB0, im2[q], KC0));   // t/2 pair
            u64 h1 = fma2(KA1, re2[q], fma2(KB1, im2[q], KC1));
            float h0l, h0h, h1l, h1h;
            unpack2(h0, h0l, h0h); unpack2(h1, h1l, h1h);
            u64 th0 = pack2(tanh_fast(h0l), tanh_fast(h0h));
            u64 th1 = pack2(tanh_fast(h1l), tanh_fast(h1h));
            u64 v0 = fma2(h0, th0, h0);    // silu = h + h*tanh(h), h = t/2
            u64 v1 = fma2(h1, th1, h1);
            U0[q] = v0; U1[q] = v1;
            #pragma unroll
            for (int h = 0; h < NHEADS; ++h) {
                u64 sc = fma2(AH0[h], v0, mul2(AH1[h], v1));
                unpack2(sc, p[(2 * q) * 4 + h], p[(2 * q + 1) * 4 + h]);
            }
        }
        // Halving butterfly: 32 warp-sums in 31 shfls; lane l ends with the
        // warp-sum of p[l] in p[0]  (score for pt=l>>2, h=l&3).
        #pragma unroll
        for (int m = 16; m >= 1; m >>= 1) {
            const bool hi = (lane & m) != 0;
            #pragma unroll
            for (int i = 0; i < m; ++i) {
                float keep = hi ? p[i + m] : p[i];
                float send = hi ? p[i] : p[i + m];
                p[i] = keep + __shfl_xor_sync(0xffffffffu, send, m);
            }
        }
        float em = exp2_fast(p[0]);   // exp(score(pt=lane>>2, h=lane&3))
        zloc += em;
        // Broadcast the 32 weights through smem (double-buffered per warp).
        wb[wid][g & 1][lane] = em;
        __syncwarp();
        const float4* wp = (const float4*)&wb[wid][g & 1][0];
        #pragma unroll
        for (int q = 0; q < 4; ++q) {
            float4 wa = wp[2 * q];       // weights for pt=2q,  h=0..3
            float4 wc = wp[2 * q + 1];   // weights for pt=2q+1, h=0..3
            float u0l, u0h, u1l, u1h;
            unpack2(U0[q], u0l, u0h); unpack2(U1[q], u1l, u1h);
            // pt = 2q
            {
                u64 W01 = pack2(wa.x, wa.y), W23 = pack2(wa.z, wa.w);
                u64 D0 = pack2(u0l, u0l), D1 = pack2(u1l, u1l);
                acc0_01 = fma2(W01, D0, acc0_01);
                acc0_23 = fma2(W23, D0, acc0_23);
                acc1_01 = fma2(W01, D1, acc1_01);
                acc1_23 = fma2(W23, D1, acc1_23);
            }
            // pt = 2q+1
            {
                u64 W01 = pack2(wc.x, wc.y), W23 = pack2(wc.z, wc.w);
                u64 D0 = pack2(u0h, u0h), D1 = pack2(u1h, u1h);
                acc0_01 = fma2(W01, D0, acc0_01);
                acc0_23 = fma2(W23, D0, acc0_23);
                acc1_01 = fma2(W01, D1, acc1_01);
                acc1_23 = fma2(W23, D1, acc1_23);
            }
        }
    }

    float acc0[NHEADS], acc1[NHEADS];
    unpack2(acc0_01, acc0[0], acc0[1]); unpack2(acc0_23, acc0[2], acc0[3]);
    unpack2(acc1_01, acc1[0], acc1[1]); unpack2(acc1_23, acc1[2], acc1[3]);

    // Tail points (N % 8): warp 0 only, scalar path.
    float ztl[NHEADS] = {0.f, 0.f, 0.f, 0.f};
    if (gwarp == 0) {
        float A0[NHEADS], A1[NHEADS];
        #pragma unroll
        for (int h = 0; h < NHEADS; ++h) { A0[h] = atil[h][j0]; A1[h] = atil[h][j1]; }
        float ka0, kb0, kc0, ka1, kb1, kc1, dum;
        unpack2(KA0, ka0, dum); unpack2(KB0, kb0, dum); unpack2(KC0, kc0, dum);
        unpack2(KA1, ka1, dum); unpack2(KB1, kb1, dum); unpack2(KC1, kc1, dum);
        for (int n = (G << 3); n < N; ++n) {
            float re = rr[n], im = ri[n];
            float h0 = fmaf(ka0, re, fmaf(kb0, im, kc0));
            float h1 = fmaf(ka1, re, fmaf(kb1, im, kc1));
            float v0 = fmaf(h0, tanh_fast(h0), h0);
            float v1 = fmaf(h1, tanh_fast(h1), h1);
            #pragma unroll
            for (int h = 0; h < NHEADS; ++h) {
                float s = fmaf(A0[h], v0, A1[h] * v1);
                #pragma unroll
                for (int m = 16; m >= 1; m >>= 1)
                    s += __shfl_xor_sync(0xffffffffu, s, m);
                float w = exp2_fast(s);
                ztl[h] += w;
                acc0[h] = fmaf(w, v0, acc0[h]);
                acc1[h] = fmaf(w, v1, acc1[h]);
            }
        }
    }

    // Commit warp partials (lane-distinct addresses; no intra-warp contention)
    #pragma unroll
    for (int h = 0; h < NHEADS; ++h) {
        atomicAdd(&g_S[h][j0], acc0[h]);
        atomicAdd(&g_S[h][j1], acc1[h]);
    }
    // zloc at lane l belongs to head h=l&3; same-h lanes differ in bits {2,3,4}
    float zs = zloc + __shfl_xor_sync(0xffffffffu, zloc, 16);
    zs += __shfl_xor_sync(0xffffffffu, zs, 8);
    zs += __shfl_xor_sync(0xffffffffu, zs, 4);
    if (lane < NHEADS) atomicAdd(&g_z[lane], zs);
    if (gwarp == 0 && lane == 0) {
        #pragma unroll
        for (int h = 0; h < NHEADS; ++h) atomicAdd(&g_z[h], ztl[h]);
    }

    // ---- epilogue: last block computes the output -------------------------
    __threadfence();
    if (t == 0) {
        unsigned v = atomicAdd(&g_ctr, 1u);
        isLast = (v == gridDim.x - 1);
        if (isLast) g_ctr = 0;           // all blocks incremented; safe reset
    }
    __syncthreads();
    if (!isLast) return;

    float* hbar = &ash[0][0];            // reuse [4][64]
    float* pooled = qsh;                 // reuse [64]
    if (t < NHEADS) invz[t] = __frcp_rn(__ldcg(&g_z[t]));
    __syncthreads();
    {
        int h = t >> 6, j = t & 63;
        float s = 0.f;
        #pragma unroll 8
        for (int m = 0; m < 64; ++m)
            s = fmaf(W2[j * 64 + m], __ldcg(&g_S[h][m]), s);
        hbar[h * 64 + j] = fmaf(s, invz[h], b2[j]);
    }
    __syncthreads();
    // scratch reset for next graph replay (all reads of g_S/g_z done)
    ((float*)g_S)[t] = 0.f;
    if (t < NHEADS) g_z[t] = 0.f;
    if (t < 64) {
        int h = t >> 4;
        float s = ipb[128 + t];          // Wv row (128+t) dot hbar_h + bv
        #pragma unroll 8
        for (int m = 0; m < 64; ++m)
            s = fmaf(ipw[(128 + t) * 64 + m], hbar[h * 64 + m], s);
        pooled[t] = s;
    }
    __syncthreads();
    if (t < 64) {
        float s = opb[t];
        #pragma unroll 8
        for (int k = 0; k < 64; ++k) s = fmaf(opw[t * 64 + k], pooled[k], s);
        out[t] = s;
    }
}

// ---------------------------------------------------------------------------
extern "C" void kernel_launch(void* const* d_in, const int* in_sizes, int n_in,
                              void* d_out, int out_size) {
    // Inputs (metadata order): rho_real, rho_imag, l_A, l_B, [Z_A, Z_B,]
    // W1, b1, W2, b2, query, in_proj_w, in_proj_b, out_proj_w, out_proj_b.
    const float* rr    = (const float*)d_in[0];
    const float* ri    = (const float*)d_in[1];
    const float* W1    = (const float*)d_in[n_in - 9];
    const float* b1    = (const float*)d_in[n_in - 8];
    const float* W2    = (const float*)d_in[n_in - 7];
    const float* b2    = (const float*)d_in[n_in - 6];
    const float* query = (const float*)d_in[n_in - 5];
    const float* ipw   = (const float*)d_in[n_in - 4];
    const float* ipb   = (const float*)d_in[n_in - 3];
    const float* opw   = (const float*)d_in[n_in - 2];
    const float* opb   = (const float*)d_in[n_in - 1];
    int N = in_sizes[0];

    main_kernel<<<296, 256>>>(rr, ri, W1, b1, W2, query, ipw, ipb,
                              b2, opw, opb, (float*)d_out, N);
}